// round 13
// baseline (speedup 1.0000x reference)
#include <cuda_runtime.h>
#include <cuda_fp16.h>
#include <cstdint>

#define OUTF 2048
#define INF  2048
#define NNZV 262144
#define NN   65536

#define NK16 (INF / 16)      // 128 k16 steps
#define NM16 (OUTF / 16)     // 128 m16 tiles
#define NN16 (NN / 16)       // 4096 n16 tiles

#define NSPLIT 4
#define SPLIT_ELEMS (((size_t)NN16 / NSPLIT) * NK16 * 32)   // 4194304 uint4 per split

// ---- device-global scratch ----
__device__ __align__(256) float g_W32[OUTF * INF];                 // 16 MB dense W accumulator
__device__ __align__(256) uint4 g_Wfrag[NM16 * NK16 * 32];         // 8 MB A-fragment-major W
__device__ __align__(256) uint4 g_Xf[(size_t)NN16 * NK16 * 32];    // 256 MB B-fragment-major x

// ---- helpers ----
__device__ __forceinline__ void mma16816(float* c, const uint4& a, uint32_t b0, uint32_t b1) {
    asm volatile(
        "mma.sync.aligned.m16n8k16.row.col.f32.f16.f16.f32 "
        "{%0,%1,%2,%3}, {%4,%5,%6,%7}, {%8,%9}, {%0,%1,%2,%3};"
        : "+f"(c[0]), "+f"(c[1]), "+f"(c[2]), "+f"(c[3])
        : "r"(a.x), "r"(a.y), "r"(a.z), "r"(a.w), "r"(b0), "r"(b1));
}
__device__ __forceinline__ uint32_t packh2(float lo, float hi) {
    __half2 h = __floats2half2_rn(lo, hi);
    return *reinterpret_cast<uint32_t*>(&h);
}
// B-fragment pack of one uint4 element (index t into g_Xf; see pack layout docs)
__device__ __forceinline__ void pack_one(const float* __restrict__ x, size_t t) {
    int lane = (int)(t & 31);
    int kk = (int)((t >> 5) & (NK16 - 1));
    int nt = (int)(t >> 12);
    int c0 = nt * 16 + (lane >> 2);
    int kb = kk * 16 + (lane & 3) * 2;
    uint4 f;
    f.x = packh2(x[(size_t)c0 * INF + kb],           x[(size_t)c0 * INF + kb + 1]);
    f.y = packh2(x[(size_t)c0 * INF + kb + 8],       x[(size_t)c0 * INF + kb + 9]);
    f.z = packh2(x[(size_t)(c0 + 8) * INF + kb],     x[(size_t)(c0 + 8) * INF + kb + 1]);
    f.w = packh2(x[(size_t)(c0 + 8) * INF + kb + 8], x[(size_t)(c0 + 8) * INF + kb + 9]);
    g_Xf[t] = f;
}

// ---- prologue kernels ----
__global__ void zero_w_kernel() {
    int i = blockIdx.x * blockDim.x + threadIdx.x;
    reinterpret_cast<float4*>(g_W32)[i] = make_float4(0.f, 0.f, 0.f, 0.f);
}
__global__ void scatter_kernel(const float* __restrict__ vals, const int* __restrict__ rows,
                               const int* __restrict__ cols) {
    int i = blockIdx.x * blockDim.x + threadIdx.x;
    atomicAdd(&g_W32[rows[i] * INF + cols[i]], vals[i]);
}
// A-fragment pack (mma.m16n8k16 row-major A)
__global__ void pack_w_kernel() {
    int t = blockIdx.x * blockDim.x + threadIdx.x;   // NM16*NK16*32
    int lane = t & 31;
    int kk = (t >> 5) & (NK16 - 1);
    int T = t >> 12;
    int r0 = T * 16 + (lane >> 2);
    int kb = kk * 16 + (lane & 3) * 2;
    const float* W = g_W32;
    uint4 f;
    f.x = packh2(W[r0 * INF + kb],           W[r0 * INF + kb + 1]);
    f.y = packh2(W[(r0 + 8) * INF + kb],     W[(r0 + 8) * INF + kb + 1]);
    f.z = packh2(W[r0 * INF + kb + 8],       W[r0 * INF + kb + 9]);
    f.w = packh2(W[(r0 + 8) * INF + kb + 8], W[(r0 + 8) * INF + kb + 9]);
    g_Wfrag[t] = f;
}
// standalone pack of x split 0 (the only exposed pack; splits 1-3 hide under gemm)
__global__ void pack_x0_kernel(const float* __restrict__ x) {
    pack_one(x, (size_t)blockIdx.x * blockDim.x + threadIdx.x);
}

// ---- fused: gemm(split s) + pack_x(split s+1) in one heterogeneous grid ----
// 2560 CTAs of 128 threads. bid%5==4 -> pack CTA (512 of them, interleaved so
// every wave carries ~20% DRAM workers under the tensor-bound gemm CTAs);
// else gemm CTA, g = (bid/5)*4 + bid%5 in 0..2047, m-fastest (16 m-tiles share
// each n-tile's B range within a wave for L2 reuse).
__global__ void __launch_bounds__(128, 2)
fused_kernel(const float* __restrict__ bias, float* __restrict__ out,
             const float* __restrict__ x, int s) {
    const int bid = blockIdx.x;
    const int r5 = bid % 5;

    if (r5 == 4) {
        // ---- pack role: split s+1 (no-op on last split) ----
        if (s + 1 < NSPLIT) {
            const size_t base = (size_t)(s + 1) * SPLIT_ELEMS + (size_t)(bid / 5) * 8192;
#pragma unroll 4
            for (int i = 0; i < 64; i++)
                pack_one(x, base + (size_t)i * 128 + threadIdx.x);
        }
        return;
    }

    // ---- gemm role ----
    const int g = (bid / 5) * 4 + r5;       // 0..2047
    const int bx = g & 15;                  // m tile (fast)
    const int by = g >> 4;                  // n tile within split
    const int lid = threadIdx.x & 31;
    const int wid = threadIdx.x >> 5;
    const int wm = wid & 1;
    const int wn = wid >> 1;
    const int m0 = bx * 128;
    const int n_tile = s * (NN / 128 / NSPLIT) + by;
    const int n0 = n_tile * 128;

    const int m16b = bx * 8 + wm * 4;
    const int n16b = n_tile * 8 + wn * 4;

    const uint4* __restrict__ Ap = g_Wfrag + ((size_t)m16b * NK16) * 32 + lid;
    const uint4* __restrict__ Bp = g_Xf   + ((size_t)n16b * NK16) * 32 + lid;
    const size_t TS = (size_t)NK16 * 32;

    float acc[4][8][4];
#pragma unroll
    for (int mt = 0; mt < 4; mt++)
#pragma unroll
        for (int nt = 0; nt < 8; nt++)
#pragma unroll
            for (int e = 0; e < 4; e++) acc[mt][nt][e] = 0.f;

    uint4 a0[4], b0[4], a1[4], b1[4], a2[4], b2[4];
#pragma unroll
    for (int i = 0; i < 4; i++) { a0[i] = __ldg(Ap + i * TS);      b0[i] = __ldg(Bp + i * TS); }
#pragma unroll
    for (int i = 0; i < 4; i++) { a1[i] = __ldg(Ap + i * TS + 32); b1[i] = __ldg(Bp + i * TS + 32); }

    auto consume = [&](const uint4* a, const uint4* b) {
#pragma unroll
        for (int mt = 0; mt < 4; mt++)
#pragma unroll
            for (int j = 0; j < 4; j++) {
                mma16816(acc[mt][2 * j],     a[mt], b[j].x, b[j].y);
                mma16816(acc[mt][2 * j + 1], a[mt], b[j].z, b[j].w);
            }
    };

    // 42 branch-free steady iterations (consume kk=0..125, prefetch to 127)
    const uint4* Ait = Ap;
    const uint4* Bit = Bp;
#pragma unroll 1
    for (int it = 0; it < 42; it++) {
#pragma unroll
        for (int i = 0; i < 4; i++) { a2[i] = __ldg(Ait + i * TS + 64); b2[i] = __ldg(Bit + i * TS + 64); }
        consume(a0, b0);
#pragma unroll
        for (int i = 0; i < 4; i++) { a0[i] = __ldg(Ait + i * TS + 96); b0[i] = __ldg(Bit + i * TS + 96); }
        consume(a1, b1);
#pragma unroll
        for (int i = 0; i < 4; i++) { a1[i] = __ldg(Ait + i * TS + 128); b1[i] = __ldg(Bit + i * TS + 128); }
        consume(a2, b2);
        Ait += 96; Bit += 96;
    }
    consume(a0, b0);   // kk = 126
    consume(a1, b1);   // kk = 127

    // ---- epilogue: out[n, o] = acc + bias[o] ----
    const int q = lid >> 2;
    const int p2 = (lid & 3) << 1;
#pragma unroll
    for (int mt = 0; mt < 4; mt++) {
        const int o_lo = m0 + wm * 64 + mt * 16 + q;
        const float bv_lo = bias[o_lo];
        const float bv_hi = bias[o_lo + 8];
#pragma unroll
        for (int j = 0; j < 4; j++)
#pragma unroll
            for (int h = 0; h < 2; h++) {
                const int n = n0 + wn * 64 + j * 16 + h * 8 + p2;
                float* o0 = out + (size_t)n * OUTF;
                float* o1 = out + (size_t)(n + 1) * OUTF;
                const float* c = acc[mt][2 * j + h];
                o0[o_lo]     = c[0] + bv_lo;
                o1[o_lo]     = c[1] + bv_lo;
                o0[o_lo + 8] = c[2] + bv_hi;
                o1[o_lo + 8] = c[3] + bv_hi;
            }
    }
}

extern "C" void kernel_launch(void* const* d_in, const int* in_sizes, int n_in,
                              void* d_out, int out_size) {
    (void)in_sizes; (void)n_in; (void)out_size;
    const float* x      = (const float*)d_in[0];
    const float* values = (const float*)d_in[1];
    const float* bias   = (const float*)d_in[2];
    const int*   rows   = (const int*)d_in[3];
    const int*   cols   = (const int*)d_in[4];
    float* out = (float*)d_out;

    zero_w_kernel<<<(OUTF * INF / 4) / 256, 256>>>();
    scatter_kernel<<<NNZV / 256, 256>>>(values, rows, cols);
    pack_w_kernel<<<(NM16 * NK16 * 32) / 256, 256>>>();
    pack_x0_kernel<<<(int)(SPLIT_ELEMS / 256), 256>>>(x);   // only exposed x-pack

    for (int s = 0; s < NSPLIT; s++) {
        fused_kernel<<<2560, 128>>>(bias, out, x, s);       // gemm(s) + pack(s+1)
    }
}

// round 14
// speedup vs baseline: 1.0209x; 1.0209x over previous
#include <cuda_runtime.h>
#include <cuda_fp16.h>
#include <cstdint>

#define OUTF 2048
#define INF  2048
#define NNZV 262144
#define NN   65536

#define NK16 (INF / 16)      // 128 k16 steps
#define NM16 (OUTF / 16)     // 128 m16 tiles
#define NN16 (NN / 16)       // 4096 n16 tiles

#define NSPLIT 4
#define NT_PER_SPLIT (NN16 / NSPLIT)          // 1024
#define UNITS_PER_SPLIT ((NT_PER_SPLIT / 2) * 8)  // 4096 (2 nt x 16 kk per unit)

#define SM_STRIDE 132        // half2 per smem row (132%32==4 -> conflict-free frag LDS)

// ---- device-global scratch ----
__device__ __align__(256) float g_W32[OUTF * INF];                 // 16 MB dense W accumulator
__device__ __align__(256) uint4 g_Wfrag[NM16 * NK16 * 32];         // 8 MB A-fragment-major W
__device__ __align__(256) uint4 g_Xf[(size_t)NN16 * NK16 * 32];    // 256 MB B-fragment-major x

// ---- helpers ----
__device__ __forceinline__ void mma16816(float* c, const uint4& a, uint32_t b0, uint32_t b1) {
    asm volatile(
        "mma.sync.aligned.m16n8k16.row.col.f32.f16.f16.f32 "
        "{%0,%1,%2,%3}, {%4,%5,%6,%7}, {%8,%9}, {%0,%1,%2,%3};"
        : "+f"(c[0]), "+f"(c[1]), "+f"(c[2]), "+f"(c[3])
        : "r"(a.x), "r"(a.y), "r"(a.z), "r"(a.w), "r"(b0), "r"(b1));
}
__device__ __forceinline__ uint32_t packh2(float lo, float hi) {
    __half2 h = __floats2half2_rn(lo, hi);
    return *reinterpret_cast<uint32_t*>(&h);
}
__device__ __forceinline__ uint32_t h2u(__half2 h) { return *reinterpret_cast<uint32_t*>(&h); }

// ---- coalesced smem-transpose pack of one unit: 2 n16-tiles x 16 kk (32 rows x 256 k) ----
// Loads: fully-coalesced LDG.128 (4 rows x 128B per warp instr). Stores: coalesced STG.128.
// Fragment LDS conflict-free via stride-132 rows. Output values/addresses bit-identical
// to the reference scalar pack.
__device__ __forceinline__ void pack_block(const float* __restrict__ x, __half2* sm,
                                           int nt0, int kc, int tid) {
    const int lr = tid >> 3;          // 0..15
    const int c8 = tid & 7;           // float4 col group
#pragma unroll
    for (int h = 0; h < 2; h++) {
        const int row_l = h * 16 + lr;
        const float* src = x + (size_t)(nt0 * 16 + row_l) * INF + kc * 256;
#pragma unroll
        for (int rnd = 0; rnd < 8; rnd++) {
            const int c4 = c8 + rnd * 8;   // 0..63
            float4 v = *reinterpret_cast<const float4*>(src + c4 * 4);
            sm[row_l * SM_STRIDE + c4 * 2]     = __floats2half2_rn(v.x, v.y);
            sm[row_l * SM_STRIDE + c4 * 2 + 1] = __floats2half2_rn(v.z, v.w);
        }
    }
    __syncthreads();
    const int w = tid >> 5, l = tid & 31;
    const int nt_l = w >> 1;              // 0..1
    const int kkh = (w & 1) * 8;          // kk half
    const int r0 = nt_l * 16 + (l >> 2);
    const int cb = l & 3;
#pragma unroll
    for (int i = 0; i < 8; i++) {
        const int kkl = kkh + i;          // 0..15
        uint4 f;
        f.x = h2u(sm[r0 * SM_STRIDE + kkl * 8 + cb]);
        f.y = h2u(sm[r0 * SM_STRIDE + kkl * 8 + cb + 4]);
        f.z = h2u(sm[(r0 + 8) * SM_STRIDE + kkl * 8 + cb]);
        f.w = h2u(sm[(r0 + 8) * SM_STRIDE + kkl * 8 + cb + 4]);
        g_Xf[((size_t)(nt0 + nt_l) * NK16 + (kc * 16 + kkl)) * 32 + l] = f;
    }
    __syncthreads();   // smem safe for next unit
}

// ---- prologue kernels ----
__global__ void zero_w_kernel() {
    int i = blockIdx.x * blockDim.x + threadIdx.x;
    reinterpret_cast<float4*>(g_W32)[i] = make_float4(0.f, 0.f, 0.f, 0.f);
}
__global__ void scatter_kernel(const float* __restrict__ vals, const int* __restrict__ rows,
                               const int* __restrict__ cols) {
    int i = blockIdx.x * blockDim.x + threadIdx.x;
    atomicAdd(&g_W32[rows[i] * INF + cols[i]], vals[i]);
}
__global__ void pack_w_kernel() {
    int t = blockIdx.x * blockDim.x + threadIdx.x;   // NM16*NK16*32
    int lane = t & 31;
    int kk = (t >> 5) & (NK16 - 1);
    int T = t >> 12;
    int r0 = T * 16 + (lane >> 2);
    int kb = kk * 16 + (lane & 3) * 2;
    const float* W = g_W32;
    uint4 f;
    f.x = packh2(W[r0 * INF + kb],           W[r0 * INF + kb + 1]);
    f.y = packh2(W[(r0 + 8) * INF + kb],     W[(r0 + 8) * INF + kb + 1]);
    f.z = packh2(W[r0 * INF + kb + 8],       W[r0 * INF + kb + 9]);
    f.w = packh2(W[(r0 + 8) * INF + kb + 8], W[(r0 + 8) * INF + kb + 9]);
    g_Wfrag[t] = f;
}
// standalone coalesced pack of x split 0 (only exposed x-pack)
__global__ void __launch_bounds__(128) pack_x0_kernel(const float* __restrict__ x) {
    __shared__ __half2 sm[32 * SM_STRIDE];
    const int u = blockIdx.x;             // 0..UNITS_PER_SPLIT-1
    pack_block(x, sm, (u >> 3) * 2, u & 7, threadIdx.x);
}

// ---- fused: gemm(split s) + coalesced pack_x(split s+1) ----
// 2560 CTAs x 128 thr: bid%5==4 -> pack CTA (512, each 8 units); else gemm CTA.
__global__ void __launch_bounds__(128, 2)
fused_kernel(const float* __restrict__ bias, float* __restrict__ out,
             const float* __restrict__ x, int s) {
    __shared__ __half2 sm[32 * SM_STRIDE];
    const int bid = blockIdx.x;
    const int r5 = bid % 5;

    if (r5 == 4) {
        if (s + 1 < NSPLIT) {
            const int base_nt = (s + 1) * NT_PER_SPLIT;
#pragma unroll 1
            for (int j = 0; j < 8; j++) {
                const int u = (bid / 5) * 8 + j;
                pack_block(x, sm, base_nt + (u >> 3) * 2, u & 7, threadIdx.x);
            }
        }
        return;
    }

    // ---- gemm role (identical to R12 mainloop) ----
    const int g = (bid / 5) * 4 + r5;       // 0..2047
    const int bx = g & 15;                  // m tile (fast -> L2 reuse of B)
    const int by = g >> 4;                  // n tile within split
    const int lid = threadIdx.x & 31;
    const int wid = threadIdx.x >> 5;
    const int wm = wid & 1;
    const int wn = wid >> 1;
    const int m0 = bx * 128;
    const int n_tile = s * (NN / 128 / NSPLIT) + by;
    const int n0 = n_tile * 128;

    const int m16b = bx * 8 + wm * 4;
    const int n16b = n_tile * 8 + wn * 4;

    const uint4* __restrict__ Ap = g_Wfrag + ((size_t)m16b * NK16) * 32 + lid;
    const uint4* __restrict__ Bp = g_Xf   + ((size_t)n16b * NK16) * 32 + lid;
    const size_t TS = (size_t)NK16 * 32;

    float acc[4][8][4];
#pragma unroll
    for (int mt = 0; mt < 4; mt++)
#pragma unroll
        for (int nt = 0; nt < 8; nt++)
#pragma unroll
            for (int e = 0; e < 4; e++) acc[mt][nt][e] = 0.f;

    uint4 a0[4], b0[4], a1[4], b1[4], a2[4], b2[4];
#pragma unroll
    for (int i = 0; i < 4; i++) { a0[i] = __ldg(Ap + i * TS);      b0[i] = __ldg(Bp + i * TS); }
#pragma unroll
    for (int i = 0; i < 4; i++) { a1[i] = __ldg(Ap + i * TS + 32); b1[i] = __ldg(Bp + i * TS + 32); }

    auto consume = [&](const uint4* a, const uint4* b) {
#pragma unroll
        for (int mt = 0; mt < 4; mt++)
#pragma unroll
            for (int j = 0; j < 4; j++) {
                mma16816(acc[mt][2 * j],     a[mt], b[j].x, b[j].y);
                mma16816(acc[mt][2 * j + 1], a[mt], b[j].z, b[j].w);
            }
    };

    const uint4* Ait = Ap;
    const uint4* Bit = Bp;
#pragma unroll 1
    for (int it = 0; it < 42; it++) {
#pragma unroll
        for (int i = 0; i < 4; i++) { a2[i] = __ldg(Ait + i * TS + 64); b2[i] = __ldg(Bit + i * TS + 64); }
        consume(a0, b0);
#pragma unroll
        for (int i = 0; i < 4; i++) { a0[i] = __ldg(Ait + i * TS + 96); b0[i] = __ldg(Bit + i * TS + 96); }
        consume(a1, b1);
#pragma unroll
        for (int i = 0; i < 4; i++) { a1[i] = __ldg(Ait + i * TS + 128); b1[i] = __ldg(Bit + i * TS + 128); }
        consume(a2, b2);
        Ait += 96; Bit += 96;
    }
    consume(a0, b0);   // kk = 126
    consume(a1, b1);   // kk = 127

    // ---- epilogue ----
    const int q = lid >> 2;
    const int p2 = (lid & 3) << 1;
#pragma unroll
    for (int mt = 0; mt < 4; mt++) {
        const int o_lo = m0 + wm * 64 + mt * 16 + q;
        const float bv_lo = bias[o_lo];
        const float bv_hi = bias[o_lo + 8];
#pragma unroll
        for (int j = 0; j < 4; j++)
#pragma unroll
            for (int h = 0; h < 2; h++) {
                const int n = n0 + wn * 64 + j * 16 + h * 8 + p2;
                float* o0 = out + (size_t)n * OUTF;
                float* o1 = out + (size_t)(n + 1) * OUTF;
                const float* c = acc[mt][2 * j + h];
                o0[o_lo]     = c[0] + bv_lo;
                o1[o_lo]     = c[1] + bv_lo;
                o0[o_lo + 8] = c[2] + bv_hi;
                o1[o_lo + 8] = c[3] + bv_hi;
            }
    }
}

extern "C" void kernel_launch(void* const* d_in, const int* in_sizes, int n_in,
                              void* d_out, int out_size) {
    (void)in_sizes; (void)n_in; (void)out_size;
    const float* x      = (const float*)d_in[0];
    const float* values = (const float*)d_in[1];
    const float* bias   = (const float*)d_in[2];
    const int*   rows   = (const int*)d_in[3];
    const int*   cols   = (const int*)d_in[4];
    float* out = (float*)d_out;

    zero_w_kernel<<<(OUTF * INF / 4) / 256, 256>>>();
    scatter_kernel<<<NNZV / 256, 256>>>(values, rows, cols);
    pack_w_kernel<<<(NM16 * NK16 * 32) / 256, 256>>>();
    pack_x0_kernel<<<UNITS_PER_SPLIT, 128>>>(x);            // only exposed x-pack

    for (int s = 0; s < NSPLIT; s++) {
        fused_kernel<<<2560, 128>>>(bias, out, x, s);       // gemm(s) + pack(s+1)
    }
}